// round 2
// baseline (speedup 1.0000x reference)
#include <cuda_runtime.h>
#include <math.h>

#define BATCH 512
#define SEQ   256
#define EMB   384
#define MTOT  (BATCH*SEQ)

// Scratch (allocation-free rule: static __device__ globals)
__device__ float g_qkv[(size_t)MTOT * 3 * EMB];   // [B*T, 1152] : q|k|v
__device__ float g_att[(size_t)BATCH * SEQ * SEQ]; // [B, T, T]
__device__ float g_o  [(size_t)MTOT * EMB];        // [B*T, 384]

#define BM 64
#define BN 64
#define BK 16

// Generic 64x64x16 SMEM-tiled SGEMM, 256 threads, 4x4 microtile.
// B_NT: B is [N,K] row-major (used for q@k^T). CAUSAL: mask n>m to -inf.
template<bool B_NT, bool CAUSAL>
__global__ void __launch_bounds__(256) gemm64(
    const float* __restrict__ A, int lda, size_t a_bs,
    const float* __restrict__ B, int ldb, size_t b_bs,
    float* __restrict__ Cm, int ldc, size_t c_bs,
    int K, const float* __restrict__ bias, float scale)
{
    __shared__ float As[BK][BM];
    __shared__ float Bs[BK][BN];

    const int bz = blockIdx.z;
    A  += (size_t)bz * a_bs;
    B  += (size_t)bz * b_bs;
    Cm += (size_t)bz * c_bs;

    const int m0 = blockIdx.y * BM;
    const int n0 = blockIdx.x * BN;
    const int tid = threadIdx.x;
    const int tx = tid & 15, ty = tid >> 4;

    if (CAUSAL && n0 > m0 + BM - 1) {
        // Tile entirely above the diagonal: just fill -inf.
        #pragma unroll
        for (int i = 0; i < 4; i++) {
            int m = m0 + ty * 4 + i;
            #pragma unroll
            for (int j = 0; j < 4; j++)
                Cm[(size_t)m * ldc + n0 + tx * 4 + j] = -INFINITY;
        }
        return;
    }

    const int ar = tid >> 2, ac = tid & 3;      // A tile load (64 rows x 4 float4)
    const int bkr = tid >> 4, bnc = tid & 15;   // B tile load, NN
    const int nr = tid >> 2, kc = tid & 3;      // B tile load, NT

    float acc[4][4] = {};

    for (int k0 = 0; k0 < K; k0 += BK) {
        float4 a4 = *(const float4*)(A + (size_t)(m0 + ar) * lda + k0 + ac * 4);
        As[ac*4+0][ar] = a4.x; As[ac*4+1][ar] = a4.y;
        As[ac*4+2][ar] = a4.z; As[ac*4+3][ar] = a4.w;

        if (B_NT) {
            float4 b4 = *(const float4*)(B + (size_t)(n0 + nr) * ldb + k0 + kc * 4);
            Bs[kc*4+0][nr] = b4.x; Bs[kc*4+1][nr] = b4.y;
            Bs[kc*4+2][nr] = b4.z; Bs[kc*4+3][nr] = b4.w;
        } else {
            *(float4*)(&Bs[bkr][bnc * 4]) =
                *(const float4*)(B + (size_t)(k0 + bkr) * ldb + n0 + bnc * 4);
        }
        __syncthreads();

        #pragma unroll
        for (int k = 0; k < BK; k++) {
            float4 av = *(const float4*)(&As[k][ty * 4]);
            float4 bv = *(const float4*)(&Bs[k][tx * 4]);
            float af[4] = {av.x, av.y, av.z, av.w};
            float bf[4] = {bv.x, bv.y, bv.z, bv.w};
            #pragma unroll
            for (int i = 0; i < 4; i++)
                #pragma unroll
                for (int j = 0; j < 4; j++)
                    acc[i][j] = fmaf(af[i], bf[j], acc[i][j]);
        }
        __syncthreads();
    }

    #pragma unroll
    for (int i = 0; i < 4; i++) {
        int m = m0 + ty * 4 + i;
        #pragma unroll
        for (int j = 0; j < 4; j++) {
            int n = n0 + tx * 4 + j;
            float v = acc[i][j] * scale;
            if (bias) v += __ldg(bias + n);
            if (CAUSAL && n > m) v = -INFINITY;
            Cm[(size_t)m * ldc + n] = v;
        }
    }
}

// Row softmax over T=256 entries; one block (256 threads) per row.
__global__ void __launch_bounds__(SEQ) softmax_rows(float* __restrict__ att)
{
    float* p = att + (size_t)blockIdx.x * SEQ;
    const int t = threadIdx.x;
    const int lane = t & 31, w = t >> 5;

    float v = p[t];
    __shared__ float r1[8], r2[8];

    float m = v;
    #pragma unroll
    for (int o = 16; o; o >>= 1) m = fmaxf(m, __shfl_xor_sync(0xffffffffu, m, o));
    if (lane == 0) r1[w] = m;
    __syncthreads();
    m = r1[0];
    #pragma unroll
    for (int i = 1; i < 8; i++) m = fmaxf(m, r1[i]);

    float e = expf(v - m);          // masked (-inf) entries -> 0
    float s = e;
    #pragma unroll
    for (int o = 16; o; o >>= 1) s += __shfl_xor_sync(0xffffffffu, s, o);
    if (lane == 0) r2[w] = s;
    __syncthreads();
    s = r2[0];
    #pragma unroll
    for (int i = 1; i < 8; i++) s += r2[i];

    p[t] = e * (1.0f / s);
}

extern "C" void kernel_launch(void* const* d_in, const int* in_sizes, int n_in,
                              void* d_out, int out_size)
{
    const float* x     = (const float*)d_in[0];
    const float* Wqkv  = (const float*)d_in[1];
    const float* bqkv  = (const float*)d_in[2];
    const float* Wproj = (const float*)d_in[3];
    const float* bproj = (const float*)d_in[4];
    float* out = (float*)d_out;

    float *qkv = nullptr, *att = nullptr, *o = nullptr;
    cudaGetSymbolAddress((void**)&qkv, g_qkv);
    cudaGetSymbolAddress((void**)&att, g_att);
    cudaGetSymbolAddress((void**)&o,   g_o);

    const float scale = 0.05103103630798288f;  // 1/sqrt(384)

    // 1) qkv = x @ W_qkv + b_qkv       [131072 x 1152], K=384
    gemm64<false, false><<<dim3(3 * EMB / BN, MTOT / BM, 1), 256>>>(
        x, EMB, 0, Wqkv, 3 * EMB, 0, qkv, 3 * EMB, 0, EMB, bqkv, 1.0f);

    // 2) att = (q @ k^T) * scale, causal-masked   per-batch [256x256], K=384
    gemm64<true, true><<<dim3(SEQ / BN, SEQ / BM, BATCH), 256>>>(
        qkv, 3 * EMB, (size_t)SEQ * 3 * EMB,
        qkv + EMB, 3 * EMB, (size_t)SEQ * 3 * EMB,
        att, SEQ, (size_t)SEQ * SEQ, EMB, nullptr, scale);

    // 3) softmax rows
    softmax_rows<<<BATCH * SEQ, SEQ>>>(att);

    // 4) o = att @ v                   per-batch [256x384], K=256
    gemm64<false, false><<<dim3(EMB / BN, SEQ / BM, BATCH), 256>>>(
        att, SEQ, (size_t)SEQ * SEQ,
        qkv + 2 * EMB, 3 * EMB, (size_t)SEQ * 3 * EMB,
        o, EMB, (size_t)SEQ * EMB, SEQ, nullptr, 1.0f);

    // 5) out = o @ W_proj + b_proj     [131072 x 384], K=384
    gemm64<false, false><<<dim3(EMB / BN, MTOT / BM, 1), 256>>>(
        o, EMB, 0, Wproj, EMB, 0, out, EMB, 0, EMB, bproj, 1.0f);
}

// round 3
// speedup vs baseline: 2.8885x; 2.8885x over previous
#include <cuda_runtime.h>
#include <math.h>

#define BATCH 512
#define SEQ   256
#define EMB   384
#define MTOT  (BATCH*SEQ)

// Scratch (allocation-free rule: static __device__ globals)
__device__ float g_qkv[(size_t)MTOT * 3 * EMB];    // [B*T, 1152] : q|k|v
__device__ float g_att[(size_t)BATCH * SEQ * SEQ]; // [B, T, T]
__device__ float g_o  [(size_t)MTOT * EMB];        // [B*T, 384]

#define BM 128
#define BN 64
#define BK 32
#define AS_S 36   // As row stride (words): 4m+k bank map bijective -> conflict-free frags
#define BS_S 72   // Bs row stride (words): 8k+n bank map bijective -> conflict-free frags

__device__ __forceinline__ unsigned f2tf32(float v) {
    unsigned r;
    asm("cvt.rna.tf32.f32 %0, %1;" : "=r"(r) : "f"(v));
    return r;
}

__device__ __forceinline__ void mma_tf32(float c[4], const unsigned a[4], const unsigned b[2]) {
    asm volatile(
        "mma.sync.aligned.m16n8k8.row.col.f32.tf32.tf32.f32 "
        "{%0,%1,%2,%3}, {%4,%5,%6,%7}, {%8,%9}, {%0,%1,%2,%3};"
        : "+f"(c[0]), "+f"(c[1]), "+f"(c[2]), "+f"(c[3])
        : "r"(a[0]), "r"(a[1]), "r"(a[2]), "r"(a[3]), "r"(b[0]), "r"(b[1]));
}

// tf32 tensor-core GEMM: C[M,N] = scale * (A[M,K] @ B) (+bias) (+causal mask)
// B_NT: B stored [N,K] row-major (q@k^T). Otherwise B is [K,N] row-major.
template<bool B_NT, bool CAUSAL>
__global__ void __launch_bounds__(256) gemm_tf32(
    const float* __restrict__ A, int lda, size_t a_bs,
    const float* __restrict__ B, int ldb, size_t b_bs,
    float* __restrict__ Cm, int ldc, size_t c_bs,
    int K, const float* __restrict__ bias, float scale)
{
    __shared__ unsigned As[BM * AS_S];   // 18.4 KB
    __shared__ unsigned Bs[BK * BS_S];   //  9.2 KB

    const int bz = blockIdx.z;
    A  += (size_t)bz * a_bs;
    B  += (size_t)bz * b_bs;
    Cm += (size_t)bz * c_bs;

    const int m0 = blockIdx.y * BM;
    const int n0 = blockIdx.x * BN;
    const int tid = threadIdx.x;
    const int lane = tid & 31, wid = tid >> 5;
    const int wm = (wid & 3) * 32;       // 4 warps along M
    const int wn = (wid >> 2) * 32;      // 2 warps along N
    const int gi = lane >> 2, tg = lane & 3;

    if (CAUSAL && n0 > m0 + BM - 1) {
        // tile entirely above diagonal: fill -inf, skip compute
        const float4 NI = make_float4(-INFINITY, -INFINITY, -INFINITY, -INFINITY);
        #pragma unroll
        for (int r = tid; r < BM * BN / 4; r += 256) {
            int m = r >> 4, nq = r & 15;
            *(float4*)&Cm[(size_t)(m0 + m) * ldc + n0 + nq * 4] = NI;
        }
        return;
    }

    float acc[2][4][4] = {};

    for (int k0 = 0; k0 < K; k0 += BK) {
        // ---- stage A tile: BM x BK, coalesced float4 along K ----
        #pragma unroll
        for (int r = tid; r < BM * BK / 4; r += 256) {
            int m = r >> 3, kq = r & 7;
            float4 v = *(const float4*)(A + (size_t)(m0 + m) * lda + k0 + kq * 4);
            As[m * AS_S + kq * 4 + 0] = f2tf32(v.x);
            As[m * AS_S + kq * 4 + 1] = f2tf32(v.y);
            As[m * AS_S + kq * 4 + 2] = f2tf32(v.z);
            As[m * AS_S + kq * 4 + 3] = f2tf32(v.w);
        }
        // ---- stage B tile into Bs[k][n] ----
        if (B_NT) {
            #pragma unroll
            for (int r = tid; r < BN * BK / 4; r += 256) {
                int n = r >> 3, kq = r & 7;  // coalesced float4 along K
                float4 v = *(const float4*)(B + (size_t)(n0 + n) * ldb + k0 + kq * 4);
                Bs[(kq * 4 + 0) * BS_S + n] = f2tf32(v.x);
                Bs[(kq * 4 + 1) * BS_S + n] = f2tf32(v.y);
                Bs[(kq * 4 + 2) * BS_S + n] = f2tf32(v.z);
                Bs[(kq * 4 + 3) * BS_S + n] = f2tf32(v.w);
            }
        } else {
            #pragma unroll
            for (int r = tid; r < BN * BK / 4; r += 256) {
                int k = r >> 4, nq = r & 15; // coalesced float4 along N
                float4 v = *(const float4*)(B + (size_t)(k0 + k) * ldb + n0 + nq * 4);
                uint4 t;
                t.x = f2tf32(v.x); t.y = f2tf32(v.y);
                t.z = f2tf32(v.z); t.w = f2tf32(v.w);
                *(uint4*)&Bs[k * BS_S + nq * 4] = t;
            }
        }
        __syncthreads();

        // ---- 4 k8 steps of m16n8k8 ----
        #pragma unroll
        for (int ks = 0; ks < 4; ks++) {
            unsigned a[2][4], b[4][2];
            const int kk = ks * 8 + tg;
            #pragma unroll
            for (int i = 0; i < 2; i++) {
                int m = wm + i * 16 + gi;
                a[i][0] = As[m * AS_S + kk];
                a[i][1] = As[(m + 8) * AS_S + kk];
                a[i][2] = As[m * AS_S + kk + 4];
                a[i][3] = As[(m + 8) * AS_S + kk + 4];
            }
            #pragma unroll
            for (int j = 0; j < 4; j++) {
                int n = wn + j * 8 + gi;
                b[j][0] = Bs[kk * BS_S + n];
                b[j][1] = Bs[(kk + 4) * BS_S + n];
            }
            #pragma unroll
            for (int i = 0; i < 2; i++)
                #pragma unroll
                for (int j = 0; j < 4; j++)
                    mma_tf32(acc[i][j], a[i], b[j]);
        }
        __syncthreads();
    }

    // ---- epilogue: scale, bias, causal mask, float2 stores ----
    #pragma unroll
    for (int i = 0; i < 2; i++) {
        #pragma unroll
        for (int j = 0; j < 4; j++) {
            int m = m0 + wm + i * 16 + gi;
            int n = n0 + wn + j * 8 + tg * 2;
            float bb0 = 0.f, bb1 = 0.f;
            if (bias) { bb0 = __ldg(bias + n); bb1 = __ldg(bias + n + 1); }
            #pragma unroll
            for (int h = 0; h < 2; h++) {   // h=0 -> rows m, h=1 -> rows m+8
                int mm = m + h * 8;
                float v0 = acc[i][j][h * 2 + 0] * scale + bb0;
                float v1 = acc[i][j][h * 2 + 1] * scale + bb1;
                if (CAUSAL) {
                    if (n > mm)     v0 = -INFINITY;
                    if (n + 1 > mm) v1 = -INFINITY;
                }
                float2 p = make_float2(v0, v1);
                *(float2*)&Cm[(size_t)mm * ldc + n] = p;
            }
        }
    }
}

// Row softmax over T=256 entries; one block (256 threads) per row.
__global__ void __launch_bounds__(SEQ) softmax_rows(float* __restrict__ att)
{
    float* p = att + (size_t)blockIdx.x * SEQ;
    const int t = threadIdx.x;
    const int lane = t & 31, w = t >> 5;

    float v = p[t];
    __shared__ float r1[8], r2[8];

    float m = v;
    #pragma unroll
    for (int o = 16; o; o >>= 1) m = fmaxf(m, __shfl_xor_sync(0xffffffffu, m, o));
    if (lane == 0) r1[w] = m;
    __syncthreads();
    m = r1[0];
    #pragma unroll
    for (int i = 1; i < 8; i++) m = fmaxf(m, r1[i]);

    float e = expf(v - m);
    float s = e;
    #pragma unroll
    for (int o = 16; o; o >>= 1) s += __shfl_xor_sync(0xffffffffu, s, o);
    if (lane == 0) r2[w] = s;
    __syncthreads();
    s = r2[0];
    #pragma unroll
    for (int i = 1; i < 8; i++) s += r2[i];

    p[t] = e * (1.0f / s);
}

extern "C" void kernel_launch(void* const* d_in, const int* in_sizes, int n_in,
                              void* d_out, int out_size)
{
    const float* x     = (const float*)d_in[0];
    const float* Wqkv  = (const float*)d_in[1];
    const float* bqkv  = (const float*)d_in[2];
    const float* Wproj = (const float*)d_in[3];
    const float* bproj = (const float*)d_in[4];
    float* out = (float*)d_out;

    float *qkv = nullptr, *att = nullptr, *o = nullptr;
    cudaGetSymbolAddress((void**)&qkv, g_qkv);
    cudaGetSymbolAddress((void**)&att, g_att);
    cudaGetSymbolAddress((void**)&o,   g_o);

    const float scale = 0.05103103630798288f;  // 1/sqrt(384)

    // 1) qkv = x @ W_qkv + b_qkv       [131072 x 1152], K=384
    gemm_tf32<false, false><<<dim3(3 * EMB / BN, MTOT / BM, 1), 256>>>(
        x, EMB, 0, Wqkv, 3 * EMB, 0, qkv, 3 * EMB, 0, EMB, bqkv, 1.0f);

    // 2) att = (q @ k^T) * scale, causal-masked   per-batch [256x256], K=384
    gemm_tf32<true, true><<<dim3(SEQ / BN, SEQ / BM, BATCH), 256>>>(
        qkv, 3 * EMB, (size_t)SEQ * 3 * EMB,
        qkv + EMB, 3 * EMB, (size_t)SEQ * 3 * EMB,
        att, SEQ, (size_t)SEQ * SEQ, EMB, nullptr, scale);

    // 3) softmax rows
    softmax_rows<<<BATCH * SEQ, SEQ>>>(att);

    // 4) o = att @ v                   per-batch [256x384], K=256
    gemm_tf32<false, false><<<dim3(EMB / BN, SEQ / BM, BATCH), 256>>>(
        att, SEQ, (size_t)SEQ * SEQ,
        qkv + 2 * EMB, 3 * EMB, (size_t)SEQ * 3 * EMB,
        o, EMB, (size_t)SEQ * EMB, SEQ, nullptr, 1.0f);

    // 5) out = o @ W_proj + b_proj     [131072 x 384], K=384
    gemm_tf32<false, false><<<dim3(EMB / BN, MTOT / BM, 1), 256>>>(
        o, EMB, 0, Wproj, EMB, 0, out, EMB, 0, EMB, bproj, 1.0f);
}

// round 4
// speedup vs baseline: 3.0668x; 1.0617x over previous
#include <cuda_runtime.h>
#include <math.h>

#define BATCH 512
#define SEQ   256
#define EMB   384
#define MTOT  (BATCH*SEQ)

// Scratch (allocation-free rule: static __device__ globals)
__device__ float g_qkv[(size_t)MTOT * 3 * EMB];    // [B*T, 1152] : q|k|v
__device__ float g_o  [(size_t)MTOT * EMB];        // [B*T, 384]

#define BM 128
#define BN 64
#define BK 32
#define AS_S 36   // ≡4 mod 32: A-frag (4m+k) conflict-free
#define BS_S 72   // ≡8 mod 32: B-frag (8k+n) conflict-free

__device__ __forceinline__ unsigned f2tf32(float v) {
    unsigned r;
    asm("cvt.rna.tf32.f32 %0, %1;" : "=r"(r) : "f"(v));
    return r;
}

__device__ __forceinline__ void mma_tf32(float c[4], const unsigned a[4], const unsigned b[2]) {
    asm volatile(
        "mma.sync.aligned.m16n8k8.row.col.f32.tf32.tf32.f32 "
        "{%0,%1,%2,%3}, {%4,%5,%6,%7}, {%8,%9}, {%0,%1,%2,%3};"
        : "+f"(c[0]), "+f"(c[1]), "+f"(c[2]), "+f"(c[3])
        : "r"(a[0]), "r"(a[1]), "r"(a[2]), "r"(a[3]), "r"(b[0]), "r"(b[1]));
}

// ============================ dense GEMM (qkv, proj) ============================
__global__ void __launch_bounds__(256) gemm_tf32(
    const float* __restrict__ A, int lda,
    const float* __restrict__ B, int ldb,
    float* __restrict__ Cm, int ldc,
    int K, const float* __restrict__ bias)
{
    __shared__ unsigned As[BM * AS_S];
    __shared__ unsigned Bs[BK * BS_S];

    const int m0 = blockIdx.y * BM;
    const int n0 = blockIdx.x * BN;
    const int tid = threadIdx.x;
    const int lane = tid & 31, wid = tid >> 5;
    const int wm = (wid & 3) * 32;
    const int wn = (wid >> 2) * 32;
    const int gi = lane >> 2, tg = lane & 3;

    float acc[2][4][4] = {};

    for (int k0 = 0; k0 < K; k0 += BK) {
        #pragma unroll
        for (int r = tid; r < BM * BK / 4; r += 256) {
            int m = r >> 3, kq = r & 7;
            float4 v = *(const float4*)(A + (size_t)(m0 + m) * lda + k0 + kq * 4);
            As[m * AS_S + kq * 4 + 0] = f2tf32(v.x);
            As[m * AS_S + kq * 4 + 1] = f2tf32(v.y);
            As[m * AS_S + kq * 4 + 2] = f2tf32(v.z);
            As[m * AS_S + kq * 4 + 3] = f2tf32(v.w);
        }
        #pragma unroll
        for (int r = tid; r < BN * BK / 4; r += 256) {
            int k = r >> 4, nq = r & 15;
            float4 v = *(const float4*)(B + (size_t)(k0 + k) * ldb + n0 + nq * 4);
            uint4 t;
            t.x = f2tf32(v.x); t.y = f2tf32(v.y);
            t.z = f2tf32(v.z); t.w = f2tf32(v.w);
            *(uint4*)&Bs[k * BS_S + nq * 4] = t;
        }
        __syncthreads();

        #pragma unroll
        for (int ks = 0; ks < 4; ks++) {
            unsigned a[2][4], b[4][2];
            const int kk = ks * 8 + tg;
            #pragma unroll
            for (int i = 0; i < 2; i++) {
                int m = wm + i * 16 + gi;
                a[i][0] = As[m * AS_S + kk];
                a[i][1] = As[(m + 8) * AS_S + kk];
                a[i][2] = As[m * AS_S + kk + 4];
                a[i][3] = As[(m + 8) * AS_S + kk + 4];
            }
            #pragma unroll
            for (int j = 0; j < 4; j++) {
                int n = wn + j * 8 + gi;
                b[j][0] = Bs[kk * BS_S + n];
                b[j][1] = Bs[(kk + 4) * BS_S + n];
            }
            #pragma unroll
            for (int i = 0; i < 2; i++)
                #pragma unroll
                for (int j = 0; j < 4; j++)
                    mma_tf32(acc[i][j], a[i], b[j]);
        }
        __syncthreads();
    }

    #pragma unroll
    for (int i = 0; i < 2; i++)
        #pragma unroll
        for (int j = 0; j < 4; j++) {
            int m = m0 + wm + i * 16 + gi;
            int n = n0 + wn + j * 8 + tg * 2;
            float b0 = bias ? __ldg(bias + n)     : 0.f;
            float b1 = bias ? __ldg(bias + n + 1) : 0.f;
            *(float2*)&Cm[(size_t)m * ldc + n] =
                make_float2(acc[i][j][0] + b0, acc[i][j][1] + b1);
            *(float2*)&Cm[(size_t)(m + 8) * ldc + n] =
                make_float2(acc[i][j][2] + b0, acc[i][j][3] + b1);
        }
}

// ===================== fused causal attention (flash-style) =====================
// One CTA = one (batch, 64-row Q block). S kept in SMEM, softmax in SMEM,
// P re-stored as tf32 and fed to P@V. att never touches HBM.
#define SS_S 260   // ≡4 mod 32
#define QS_S 36    // ≡4 mod 32
#define KS_S 264   // ≡8 mod 32
#define VS_S 136   // ≡8 mod 32
#define FL_SMEM (64*SS_S*4 + 64*QS_S*4 + 32*KS_S*4)   // 109568 B

__global__ void __launch_bounds__(256) flash_attn(
    const float* __restrict__ qkv, float* __restrict__ O)
{
    extern __shared__ unsigned char sm8[];
    float*    Ss = (float*)sm8;                                  // 64 x 260
    unsigned* Pu = (unsigned*)sm8;                               // P as tf32 bits
    unsigned* Qs = (unsigned*)(sm8 + 64*SS_S*4);                 // 64 x 36
    unsigned* Ks = (unsigned*)(sm8 + 64*SS_S*4 + 64*QS_S*4);     // 32 x 264
    unsigned* Vs = Ks;                                           // alias (32 x 136)

    const int b  = blockIdx.y;
    const int m0 = blockIdx.x * 64;
    const int Ncol = m0 + 64;                 // causal: live columns
    const int tid = threadIdx.x;
    const int lane = tid & 31, wid = tid >> 5;
    const int gi = lane >> 2, tg = lane & 3;
    const float scale = 0.05103103630798288f; // 1/sqrt(384)

    const float* Qp = qkv + ((size_t)b * SEQ + m0) * 1152;
    const float* Kp = qkv + (size_t)b * SEQ * 1152 + 384;
    const float* Vp = qkv + (size_t)b * SEQ * 1152 + 768;

    // ---------------- Phase 1: S = scale * Q @ K^T  (M=64, N=Ncol, K=384) ----------------
    const int wm = (wid & 1) * 32;            // 2 warps along M
    const int wn = (wid >> 1) * 64;           // 4 warps along N
    const bool wact = (wn < Ncol);

    float accS[2][8][4] = {};

    for (int k0 = 0; k0 < EMB; k0 += 32) {
        #pragma unroll
        for (int r = tid; r < 64 * 8; r += 256) {      // Q tile 64x32
            int m = r >> 3, q = r & 7;
            float4 v = *(const float4*)(Qp + (size_t)m * 1152 + k0 + q * 4);
            Qs[m * QS_S + q * 4 + 0] = f2tf32(v.x);
            Qs[m * QS_S + q * 4 + 1] = f2tf32(v.y);
            Qs[m * QS_S + q * 4 + 2] = f2tf32(v.z);
            Qs[m * QS_S + q * 4 + 3] = f2tf32(v.w);
        }
        for (int r = tid; r < Ncol * 8; r += 256) {    // K tile Ncol x 32 (transposed)
            int n = r >> 3, q = r & 7;
            float4 v = *(const float4*)(Kp + (size_t)n * 1152 + k0 + q * 4);
            Ks[(q * 4 + 0) * KS_S + n] = f2tf32(v.x);
            Ks[(q * 4 + 1) * KS_S + n] = f2tf32(v.y);
            Ks[(q * 4 + 2) * KS_S + n] = f2tf32(v.z);
            Ks[(q * 4 + 3) * KS_S + n] = f2tf32(v.w);
        }
        __syncthreads();

        if (wact) {
            #pragma unroll
            for (int ks = 0; ks < 4; ks++) {
                const int kk = ks * 8 + tg;
                unsigned a[2][4], bf[8][2];
                #pragma unroll
                for (int i = 0; i < 2; i++) {
                    int m = wm + i * 16 + gi;
                    a[i][0] = Qs[m * QS_S + kk];
                    a[i][1] = Qs[(m + 8) * QS_S + kk];
                    a[i][2] = Qs[m * QS_S + kk + 4];
                    a[i][3] = Qs[(m + 8) * QS_S + kk + 4];
                }
                #pragma unroll
                for (int j = 0; j < 8; j++) {
                    int n = wn + j * 8 + gi;
                    bf[j][0] = Ks[kk * KS_S + n];
                    bf[j][1] = Ks[(kk + 4) * KS_S + n];
                }
                #pragma unroll
                for (int i = 0; i < 2; i++)
                    #pragma unroll
                    for (int j = 0; j < 8; j++)
                        mma_tf32(accS[i][j], a[i], bf[j]);
            }
        }
        __syncthreads();
    }

    // write S (scaled + causal mask) to SMEM
    if (wact) {
        #pragma unroll
        for (int i = 0; i < 2; i++)
            #pragma unroll
            for (int j = 0; j < 8; j++) {
                int ml = wm + i * 16 + gi;
                int nl = wn + j * 8 + tg * 2;
                int r0 = m0 + ml, r8 = r0 + 8;
                float v0 = accS[i][j][0] * scale, v1 = accS[i][j][1] * scale;
                float v2 = accS[i][j][2] * scale, v3 = accS[i][j][3] * scale;
                if (nl     > r0) v0 = -INFINITY;
                if (nl + 1 > r0) v1 = -INFINITY;
                if (nl     > r8) v2 = -INFINITY;
                if (nl + 1 > r8) v3 = -INFINITY;
                *(float2*)&Ss[ml * SS_S + nl]       = make_float2(v0, v1);
                *(float2*)&Ss[(ml + 8) * SS_S + nl] = make_float2(v2, v3);
            }
    }
    __syncthreads();

    // ---------------- softmax: 4 lanes per row, 64 cols each ----------------
    {
        const int row = tid >> 2, seg = tid & 3;
        const int base = row * SS_S + seg * 64;
        const bool act = (seg * 64 < Ncol);

        float mx = -INFINITY;
        if (act) {
            #pragma unroll
            for (int i = 0; i < 16; i++) {
                float4 v = *(float4*)&Ss[base + i * 4];
                mx = fmaxf(mx, fmaxf(fmaxf(v.x, v.y), fmaxf(v.z, v.w)));
            }
        }
        mx = fmaxf(mx, __shfl_xor_sync(0xffffffffu, mx, 1));
        mx = fmaxf(mx, __shfl_xor_sync(0xffffffffu, mx, 2));

        float s = 0.f;
        if (act) {
            #pragma unroll
            for (int i = 0; i < 16; i++) {
                float4 v = *(float4*)&Ss[base + i * 4];
                v.x = __expf(v.x - mx); v.y = __expf(v.y - mx);
                v.z = __expf(v.z - mx); v.w = __expf(v.w - mx);
                *(float4*)&Ss[base + i * 4] = v;
                s += v.x + v.y + v.z + v.w;
            }
        }
        s += __shfl_xor_sync(0xffffffffu, s, 1);
        s += __shfl_xor_sync(0xffffffffu, s, 2);
        float inv = 1.0f / s;

        if (act) {
            #pragma unroll
            for (int i = 0; i < 16; i++) {
                float4 v = *(float4*)&Ss[base + i * 4];
                uint4 t;
                t.x = f2tf32(v.x * inv); t.y = f2tf32(v.y * inv);
                t.z = f2tf32(v.z * inv); t.w = f2tf32(v.w * inv);
                *(uint4*)&Pu[base + i * 4] = t;
            }
        }
    }
    __syncthreads();

    // ---------------- Phase 2: O = P @ V  (M=64, N=384, K=Ncol) ----------------
    const int wm2 = (wid & 1) * 32;
    const int wn2 = (wid >> 1) * 32;          // 4 warps x 32 = 128-col chunks

    #pragma unroll
    for (int nc = 0; nc < 3; nc++) {
        float accO[2][4][4] = {};

        for (int k0 = 0; k0 < Ncol; k0 += 32) {
            #pragma unroll
            for (int r = tid; r < 32 * 32; r += 256) { // V tile 32 x 128
                int k = r >> 5, q = r & 31;
                float4 v = *(const float4*)(Vp + (size_t)(k0 + k) * 1152 + nc * 128 + q * 4);
                uint4 t;
                t.x = f2tf32(v.x); t.y = f2tf32(v.y);
                t.z = f2tf32(v.z); t.w = f2tf32(v.w);
                *(uint4*)&Vs[k * VS_S + q * 4] = t;
            }
            __syncthreads();

            #pragma unroll
            for (int ks = 0; ks < 4; ks++) {
                const int kk = ks * 8 + tg;
                unsigned a[2][4], bf[4][2];
                #pragma unroll
                for (int i = 0; i < 2; i++) {
                    int m = wm2 + i * 16 + gi;
                    a[i][0] = Pu[m * SS_S + k0 + kk];
                    a[i][1] = Pu[(m + 8) * SS_S + k0 + kk];
                    a[i][2] = Pu[m * SS_S + k0 + kk + 4];
                    a[i][3] = Pu[(m + 8) * SS_S + k0 + kk + 4];
                }
                #pragma unroll
                for (int j = 0; j < 4; j++) {
                    int n = wn2 + j * 8 + gi;
                    bf[j][0] = Vs[kk * VS_S + n];
                    bf[j][1] = Vs[(kk + 4) * VS_S + n];
                }
                #pragma unroll
                for (int i = 0; i < 2; i++)
                    #pragma unroll
                    for (int j = 0; j < 4; j++)
                        mma_tf32(accO[i][j], a[i], bf[j]);
            }
            __syncthreads();
        }

        float* Op = O + ((size_t)b * SEQ + m0) * EMB + nc * 128;
        #pragma unroll
        for (int i = 0; i < 2; i++)
            #pragma unroll
            for (int j = 0; j < 4; j++) {
                int ml = wm2 + i * 16 + gi;
                int nl = wn2 + j * 8 + tg * 2;
                *(float2*)&Op[(size_t)ml * EMB + nl] =
                    make_float2(accO[i][j][0], accO[i][j][1]);
                *(float2*)&Op[(size_t)(ml + 8) * EMB + nl] =
                    make_float2(accO[i][j][2], accO[i][j][3]);
            }
    }
}

extern "C" void kernel_launch(void* const* d_in, const int* in_sizes, int n_in,
                              void* d_out, int out_size)
{
    const float* x     = (const float*)d_in[0];
    const float* Wqkv  = (const float*)d_in[1];
    const float* bqkv  = (const float*)d_in[2];
    const float* Wproj = (const float*)d_in[3];
    const float* bproj = (const float*)d_in[4];
    float* out = (float*)d_out;

    float *qkv = nullptr, *o = nullptr;
    cudaGetSymbolAddress((void**)&qkv, g_qkv);
    cudaGetSymbolAddress((void**)&o,   g_o);

    cudaFuncSetAttribute(flash_attn, cudaFuncAttributeMaxDynamicSharedMemorySize, FL_SMEM);

    // 1) qkv = x @ W_qkv + b_qkv   [131072 x 1152], K=384
    gemm_tf32<<<dim3(3 * EMB / BN, MTOT / BM, 1), 256>>>(
        x, EMB, Wqkv, 3 * EMB, qkv, 3 * EMB, EMB, bqkv);

    // 2) fused causal attention -> g_o
    flash_attn<<<dim3(SEQ / 64, BATCH), 256, FL_SMEM>>>(qkv, o);

    // 3) out = o @ W_proj + b_proj [131072 x 384], K=384
    gemm_tf32<<<dim3(EMB / BN, MTOT / BM, 1), 256>>>(
        o, EMB, Wproj, EMB, out, EMB, EMB, bproj);
}

// round 5
// speedup vs baseline: 3.5208x; 1.1480x over previous
#include <cuda_runtime.h>
#include <math.h>

#define BATCH 512
#define SEQ   256
#define EMB   384
#define MTOT  (BATCH*SEQ)

__device__ float g_qkv[(size_t)MTOT * 3 * EMB];    // [B*T, 1152] : q|k|v
__device__ float g_o  [(size_t)MTOT * EMB];        // [B*T, 384]

__device__ __forceinline__ unsigned f2tf32(float v) {
    unsigned r;
    asm("cvt.rna.tf32.f32 %0, %1;" : "=r"(r) : "f"(v));
    return r;
}

__device__ __forceinline__ void mma_tf32(float c[4], const unsigned a[4], const unsigned b[2]) {
    asm volatile(
        "mma.sync.aligned.m16n8k8.row.col.f32.tf32.tf32.f32 "
        "{%0,%1,%2,%3}, {%4,%5,%6,%7}, {%8,%9}, {%0,%1,%2,%3};"
        : "+f"(c[0]), "+f"(c[1]), "+f"(c[2]), "+f"(c[3])
        : "r"(a[0]), "r"(a[1]), "r"(a[2]), "r"(a[3]), "r"(b[0]), "r"(b[1]));
}

// A-fragment (m16k8 tf32) via one ldmatrix.x4 from m-major smem (stride in words).
// lanes 0-15 -> rows mbase+0..15 at col kk0; lanes 16-31 -> same rows at col kk0+4.
__device__ __forceinline__ void ldsmA(unsigned a[4], const unsigned* base, int stride,
                                      int mbase, int kk0, int lane) {
    const unsigned* p = base + (size_t)(mbase + (lane & 15)) * stride + kk0 + ((lane >> 4) << 2);
    unsigned addr = (unsigned)__cvta_generic_to_shared(p);
    asm volatile("ldmatrix.sync.aligned.m8n8.x4.shared.b16 {%0,%1,%2,%3}, [%4];"
                 : "=r"(a[0]), "=r"(a[1]), "=r"(a[2]), "=r"(a[3]) : "r"(addr));
}

// ============================ dense GEMM (qkv, proj) ============================
// CTA 128x128, BK=32, 8 warps each 64x32 (2 along M, 4 along N).
#define DBM 128
#define DBN 128
#define DBK 32
#define DAS 36    // 144B rows -> ldmatrix chunk 9r mod 8 distinct (conflict-free)
#define DBS 136   // ≡8 mod 32 -> scalar B-frag conflict-free

__global__ void __launch_bounds__(256) gemm_tf32(
    const float* __restrict__ A, int lda,
    const float* __restrict__ B, int ldb,
    float* __restrict__ Cm, int ldc,
    int K, const float* __restrict__ bias)
{
    __shared__ __align__(16) unsigned As[DBM * DAS];   // 18.4 KB
    __shared__ __align__(16) unsigned Bs[DBK * DBS];   // 17.4 KB

    const int m0 = blockIdx.y * DBM;
    const int n0 = blockIdx.x * DBN;
    const int tid = threadIdx.x;
    const int lane = tid & 31, wid = tid >> 5;
    const int wm = (wid & 1) * 64;
    const int wn = (wid >> 1) * 32;
    const int gi = lane >> 2, tg = lane & 3;

    float acc[4][4][4] = {};

    for (int k0 = 0; k0 < K; k0 += DBK) {
        // stage A tile 128x32 (tf32), STS.128
        #pragma unroll
        for (int it = 0; it < 4; it++) {
            int idx = tid + it * 256;
            int m = idx >> 3, q = idx & 7;
            float4 v = *(const float4*)(A + (size_t)(m0 + m) * lda + k0 + q * 4);
            uint4 t;
            t.x = f2tf32(v.x); t.y = f2tf32(v.y);
            t.z = f2tf32(v.z); t.w = f2tf32(v.w);
            *(uint4*)&As[m * DAS + q * 4] = t;
        }
        // stage B tile 32x128 (tf32), STS.128
        #pragma unroll
        for (int it = 0; it < 4; it++) {
            int idx = tid + it * 256;
            int k = idx >> 5, n4 = idx & 31;
            float4 v = *(const float4*)(B + (size_t)(k0 + k) * ldb + n0 + n4 * 4);
            uint4 t;
            t.x = f2tf32(v.x); t.y = f2tf32(v.y);
            t.z = f2tf32(v.z); t.w = f2tf32(v.w);
            *(uint4*)&Bs[k * DBS + n4 * 4] = t;
        }
        __syncthreads();

        #pragma unroll
        for (int ks = 0; ks < 4; ks++) {
            const int kk = ks * 8;
            unsigned a[4][4], b[4][2];
            #pragma unroll
            for (int i = 0; i < 4; i++)
                ldsmA(a[i], As, DAS, wm + i * 16, kk, lane);
            #pragma unroll
            for (int j = 0; j < 4; j++) {
                int n = wn + j * 8 + gi;
                b[j][0] = Bs[(kk + tg) * DBS + n];
                b[j][1] = Bs[(kk + tg + 4) * DBS + n];
            }
            #pragma unroll
            for (int i = 0; i < 4; i++)
                #pragma unroll
                for (int j = 0; j < 4; j++)
                    mma_tf32(acc[i][j], a[i], b[j]);
        }
        __syncthreads();
    }

    #pragma unroll
    for (int i = 0; i < 4; i++)
        #pragma unroll
        for (int j = 0; j < 4; j++) {
            int m = m0 + wm + i * 16 + gi;
            int n = n0 + wn + j * 8 + tg * 2;
            float b0 = bias ? __ldg(bias + n)     : 0.f;
            float b1 = bias ? __ldg(bias + n + 1) : 0.f;
            *(float2*)&Cm[(size_t)m * ldc + n] =
                make_float2(acc[i][j][0] + b0, acc[i][j][1] + b1);
            *(float2*)&Cm[(size_t)(m + 8) * ldc + n] =
                make_float2(acc[i][j][2] + b0, acc[i][j][3] + b1);
        }
}

// ===================== fused causal attention (flash-style) =====================
#define SS_S 260   // ≡4 mod 32; 1040B rows -> ldmatrix chunk 65r ≡ r mod 8 (CF)
#define QS_S 36
#define KS_S 264   // ≡8 mod 32 (scalar B-frag CF)
#define VS_S 136   // ≡8 mod 32
#define KV_BYTES (64*VS_S*4)                      // 34816 (covers 32*KS_S*4=33792)
#define FL_SMEM (64*SS_S*4 + 64*QS_S*4 + KV_BYTES) // 110592 B -> 2 CTAs/SM

__global__ void __launch_bounds__(256) flash_attn(
    const float* __restrict__ qkv, float* __restrict__ O)
{
    extern __shared__ __align__(16) unsigned char sm8[];
    float*    Ss = (float*)sm8;                                  // 64 x 260
    unsigned* Pu = (unsigned*)sm8;                               // P as tf32 bits
    unsigned* Qs = (unsigned*)(sm8 + 64*SS_S*4);                 // 64 x 36
    unsigned* Ks = (unsigned*)(sm8 + 64*SS_S*4 + 64*QS_S*4);     // 32 x 264
    unsigned* Vs = Ks;                                           // alias (64 x 136)

    const int b  = blockIdx.y;
    const int m0 = blockIdx.x * 64;
    const int Ncol = m0 + 64;                 // causal live columns
    const int tid = threadIdx.x;
    const int lane = tid & 31, wid = tid >> 5;
    const int gi = lane >> 2, tg = lane & 3;
    const float scale = 0.05103103630798288f; // 1/sqrt(384)

    const float* Qp = qkv + ((size_t)b * SEQ + m0) * 1152;
    const float* Kp = qkv + (size_t)b * SEQ * 1152 + 384;
    const float* Vp = qkv + (size_t)b * SEQ * 1152 + 768;

    // ---------------- Phase 1: S = scale * Q @ K^T ----------------
    const int wm = (wid & 1) * 32;            // 2 warps along M
    const int wn = (wid >> 1) * 64;           // 4 warps along N
    const bool wact = (wn < Ncol);

    float accS[2][8][4] = {};

    for (int k0 = 0; k0 < EMB; k0 += 32) {
        #pragma unroll
        for (int it = 0; it < 2; it++) {      // Q tile 64x32
            int idx = tid + it * 256;
            int m = idx >> 3, q = idx & 7;
            float4 v = *(const float4*)(Qp + (size_t)m * 1152 + k0 + q * 4);
            uint4 t;
            t.x = f2tf32(v.x); t.y = f2tf32(v.y);
            t.z = f2tf32(v.z); t.w = f2tf32(v.w);
            *(uint4*)&Qs[m * QS_S + q * 4] = t;
        }
        for (int r = tid; r < Ncol * 8; r += 256) {   // K tile Ncol x 32 (transposed)
            int n = r >> 3, q = r & 7;
            float4 v = *(const float4*)(Kp + (size_t)n * 1152 + k0 + q * 4);
            Ks[(q * 4 + 0) * KS_S + n] = f2tf32(v.x);
            Ks[(q * 4 + 1) * KS_S + n] = f2tf32(v.y);
            Ks[(q * 4 + 2) * KS_S + n] = f2tf32(v.z);
            Ks[(q * 4 + 3) * KS_S + n] = f2tf32(v.w);
        }
        __syncthreads();

        if (wact) {
            #pragma unroll
            for (int ks = 0; ks < 4; ks++) {
                const int kk = ks * 8;
                unsigned a[2][4], bf[8][2];
                #pragma unroll
                for (int i = 0; i < 2; i++)
                    ldsmA(a[i], Qs, QS_S, wm + i * 16, kk, lane);
                #pragma unroll
                for (int j = 0; j < 8; j++) {
                    int n = wn + j * 8 + gi;
                    bf[j][0] = Ks[(kk + tg) * KS_S + n];
                    bf[j][1] = Ks[(kk + tg + 4) * KS_S + n];
                }
                #pragma unroll
                for (int i = 0; i < 2; i++)
                    #pragma unroll
                    for (int j = 0; j < 8; j++)
                        mma_tf32(accS[i][j], a[i], bf[j]);
            }
        }
        __syncthreads();
    }

    if (wact) {
        #pragma unroll
        for (int i = 0; i < 2; i++)
            #pragma unroll
            for (int j = 0; j < 8; j++) {
                int ml = wm + i * 16 + gi;
                int nl = wn + j * 8 + tg * 2;
                int r0 = m0 + ml, r8 = r0 + 8;
                float v0 = accS[i][j][0] * scale, v1 = accS[i][j][1] * scale;
                float v2 = accS[i][j][2] * scale, v3 = accS[i][j][3] * scale;
                if (nl     > r0) v0 = -INFINITY;
                if (nl + 1 > r0) v1 = -INFINITY;
                if (nl     > r8) v2 = -INFINITY;
                if (nl + 1 > r8) v3 = -INFINITY;
                *(float2*)&Ss[ml * SS_S + nl]       = make_float2(v0, v1);
                *(float2*)&Ss[(ml + 8) * SS_S + nl] = make_float2(v2, v3);
            }
    }
    __syncthreads();

    // ---------------- softmax: 4 lanes per row ----------------
    {
        const int row = tid >> 2, seg = tid & 3;
        const int base = row * SS_S + seg * 64;
        const bool act = (seg * 64 < Ncol);

        float mx = -INFINITY;
        if (act) {
            #pragma unroll
            for (int i = 0; i < 16; i++) {
                float4 v = *(float4*)&Ss[base + i * 4];
                mx = fmaxf(mx, fmaxf(fmaxf(v.x, v.y), fmaxf(v.z, v.w)));
            }
        }
        mx = fmaxf(mx, __shfl_xor_sync(0xffffffffu, mx, 1));
        mx = fmaxf(mx, __shfl_xor_sync(0xffffffffu, mx, 2));

        float s = 0.f;
        if (act) {
            #pragma unroll
            for (int i = 0; i < 16; i++) {
                float4 v = *(float4*)&Ss[base + i * 4];
                v.x = __expf(v.x - mx); v.y = __expf(v.y - mx);
                v.z = __expf(v.z - mx); v.w = __expf(v.w - mx);
                *(float4*)&Ss[base + i * 4] = v;
                s += v.x + v.y + v.z + v.w;
            }
        }
        s += __shfl_xor_sync(0xffffffffu, s, 1);
        s += __shfl_xor_sync(0xffffffffu, s, 2);
        float inv = 1.0f / s;

        if (act) {
            #pragma unroll
            for (int i = 0; i < 16; i++) {
                float4 v = *(float4*)&Ss[base + i * 4];
                uint4 t;
                t.x = f2tf32(v.x * inv); t.y = f2tf32(v.y * inv);
                t.z = f2tf32(v.z * inv); t.w = f2tf32(v.w * inv);
                *(uint4*)&Pu[base + i * 4] = t;
            }
        }
    }
    __syncthreads();

    // ---------------- Phase 2: O = P @ V (64-deep V chunks) ----------------
    const int wm2 = (wid & 1) * 32;
    const int wn2 = (wid >> 1) * 32;

    #pragma unroll
    for (int nc = 0; nc < 3; nc++) {
        float accO[2][4][4] = {};

        for (int k0 = 0; k0 < Ncol; k0 += 64) {
            #pragma unroll
            for (int it = 0; it < 8; it++) {   // V tile 64 x 128
                int idx = tid + it * 256;
                int k = idx >> 5, n4 = idx & 31;
                float4 v = *(const float4*)(Vp + (size_t)(k0 + k) * 1152 + nc * 128 + n4 * 4);
                uint4 t;
                t.x = f2tf32(v.x); t.y = f2tf32(v.y);
                t.z = f2tf32(v.z); t.w = f2tf32(v.w);
                *(uint4*)&Vs[k * VS_S + n4 * 4] = t;
            }
            __syncthreads();

            #pragma unroll
            for (int ks = 0; ks < 8; ks++) {
                const int kk = ks * 8;
                unsigned a[2][4], bf[4][2];
                #pragma unroll
                for (int i = 0; i < 2; i++)
                    ldsmA(a[i], Pu, SS_S, wm2 + i * 16, k0 + kk, lane);
                #pragma unroll
                for (int j = 0; j < 4; j++) {
                    int n = wn2 + j * 8 + gi;
                    bf[j][0] = Vs[(kk + tg) * VS_S + n];
                    bf[j][1] = Vs[(kk + tg + 4) * VS_S + n];
                }
                #pragma unroll
                for (int i = 0; i < 2; i++)
                    #pragma unroll
                    for (int j = 0; j < 4; j++)
                        mma_tf32(accO[i][j], a[i], bf[j]);
            }
            __syncthreads();
        }

        float* Op = O + ((size_t)b * SEQ + m0) * EMB + nc * 128;
        #pragma unroll
        for (int i = 0; i < 2; i++)
            #pragma unroll
            for (int j = 0; j < 4; j++) {
                int ml = wm2 + i * 16 + gi;
                int nl = wn2 + j * 8 + tg * 2;
                *(float2*)&Op[(size_t)ml * EMB + nl] =
                    make_float2(accO[i][j][0], accO[i][j][1]);
                *(float2*)&Op[(size_t)(ml + 8) * EMB + nl] =
                    make_float2(accO[i][j][2], accO[i][j][3]);
            }
    }
}

extern "C" void kernel_launch(void* const* d_in, const int* in_sizes, int n_in,
                              void* d_out, int out_size)
{
    const float* x     = (const float*)d_in[0];
    const float* Wqkv  = (const float*)d_in[1];
    const float* bqkv  = (const float*)d_in[2];
    const float* Wproj = (const float*)d_in[3];
    const float* bproj = (const float*)d_in[4];
    float* out = (float*)d_out;

    float *qkv = nullptr, *o = nullptr;
    cudaGetSymbolAddress((void**)&qkv, g_qkv);
    cudaGetSymbolAddress((void**)&o,   g_o);

    cudaFuncSetAttribute(flash_attn, cudaFuncAttributeMaxDynamicSharedMemorySize, FL_SMEM);

    // 1) qkv = x @ W_qkv + b_qkv   [131072 x 1152], K=384
    gemm_tf32<<<dim3(3 * EMB / DBN, MTOT / DBM, 1), 256>>>(
        x, EMB, Wqkv, 3 * EMB, qkv, 3 * EMB, EMB, bqkv);

    // 2) fused causal attention -> g_o
    flash_attn<<<dim3(SEQ / 64, BATCH), 256, FL_SMEM>>>(qkv, o);

    // 3) out = o @ W_proj + b_proj [131072 x 384], K=384
    gemm_tf32<<<dim3(EMB / DBN, MTOT / DBM, 1), 256>>>(
        o, EMB, Wproj, EMB, out, EMB, EMB, bproj);
}